// round 1
// baseline (speedup 1.0000x reference)
#include <cuda_runtime.h>

#define INV_SQRT_2PI 0.3989422804014327f

__global__ void __launch_bounds__(256) hess_gelu_kernel(
    const float4* __restrict__ x, float4* __restrict__ out, int n4)
{
    int i = blockIdx.x * blockDim.x + threadIdx.x;
    if (i >= n4) return;
    float4 v = x[i];
    float4 r;
    {
        float t = v.x * v.x;
        r.x = (2.0f - 2.0f * t) * (INV_SQRT_2PI * __expf(-0.5f * t));
    }
    {
        float t = v.y * v.y;
        r.y = (2.0f - 2.0f * t) * (INV_SQRT_2PI * __expf(-0.5f * t));
    }
    {
        float t = v.z * v.z;
        r.z = (2.0f - 2.0f * t) * (INV_SQRT_2PI * __expf(-0.5f * t));
    }
    {
        float t = v.w * v.w;
        r.w = (2.0f - 2.0f * t) * (INV_SQRT_2PI * __expf(-0.5f * t));
    }
    out[i] = r;
}

extern "C" void kernel_launch(void* const* d_in, const int* in_sizes, int n_in,
                              void* d_out, int out_size)
{
    const float* x = (const float*)d_in[0];
    float* out = (float*)d_out;
    int n = in_sizes[0];          // 16384*16384 = 268435456
    int n4 = n >> 2;              // divisible by 4
    int threads = 256;
    int blocks = (n4 + threads - 1) / threads;
    hess_gelu_kernel<<<blocks, threads>>>(
        (const float4*)x, (float4*)out, n4);
}

// round 2
// speedup vs baseline: 1.0264x; 1.0264x over previous
#include <cuda_runtime.h>

#define INV_SQRT_2PI 0.3989422804014327f

// n = 2^28 floats = 2^26 float4 = 65536 blocks * 256 threads * 4 float4/thread.
#define THREADS 256
#define VPT 4  // float4 per thread

__device__ __forceinline__ float hess(float x) {
    float t = x * x;
    return (2.0f - 2.0f * t) * (INV_SQRT_2PI * __expf(-0.5f * t));
}

__global__ void __launch_bounds__(THREADS) hess_gelu_kernel(
    const float4* __restrict__ x, float4* __restrict__ out)
{
    // Block-contiguous tile of THREADS*VPT float4s; thread accesses are
    // block-strided so each of the VPT loads is fully coalesced.
    size_t base = (size_t)blockIdx.x * (THREADS * VPT) + threadIdx.x;

    float4 v[VPT];
#pragma unroll
    for (int j = 0; j < VPT; j++) {
        const float4* p = x + base + j * THREADS;
        // streaming load (evict-first): no reuse, keep L2 clean
        asm volatile("ld.global.cs.v4.f32 {%0,%1,%2,%3}, [%4];"
                     : "=f"(v[j].x), "=f"(v[j].y), "=f"(v[j].z), "=f"(v[j].w)
                     : "l"(p));
    }

#pragma unroll
    for (int j = 0; j < VPT; j++) {
        v[j].x = hess(v[j].x);
        v[j].y = hess(v[j].y);
        v[j].z = hess(v[j].z);
        v[j].w = hess(v[j].w);
    }

#pragma unroll
    for (int j = 0; j < VPT; j++) {
        float4* p = out + base + j * THREADS;
        asm volatile("st.global.cs.v4.f32 [%0], {%1,%2,%3,%4};"
                     :: "l"(p), "f"(v[j].x), "f"(v[j].y), "f"(v[j].z), "f"(v[j].w)
                     : "memory");
    }
}

extern "C" void kernel_launch(void* const* d_in, const int* in_sizes, int n_in,
                              void* d_out, int out_size)
{
    const float* x = (const float*)d_in[0];
    float* out = (float*)d_out;
    int n = in_sizes[0];                       // 268435456
    int n4 = n >> 2;                           // 2^26 float4
    int blocks = n4 / (THREADS * VPT);         // 65536, exact
    hess_gelu_kernel<<<blocks, THREADS>>>((const float4*)x, (float4*)out);
}